// round 1
// baseline (speedup 1.0000x reference)
#include <cuda_runtime.h>
#include <cstdint>
#include <math.h>

// Problem constants
#define BB    2
#define TT    32
#define HH    18
#define WW    32
#define DIM   1024
#define HEADS 16
#define HD    64
#define ROT   32
#define HWP   (HH*WW)            // 576
#define MTOK  (BB*TT*HWP)        // 36864 tokens
#define EQKV  (3*HEADS*HD)       // 3072
#define EO    (HEADS*HD)         // 1024

// Scratch (no allocations allowed -> device globals)
__device__ float g_qkv[(size_t)MTOK * EQKV];   // raw qkv, row-major [token][3072]
__device__ float g_att[(size_t)MTOK * EO];     // attention output, [token][1024]

// ---------------------------------------------------------------------------
// SGEMM: C[m,n] = sum_k A[m,k]*B[n,k] (+bias[n]); A:[M,K] B:[N,K] row-major.
// 128x128 tile, BK=8, 256 threads, 8x8 per-thread, smem double buffered.
// M,N,K all multiples of tile dims for this problem (no bounds checks).
// ---------------------------------------------------------------------------
#define BM 128
#define BN 128
#define BK 8

__global__ void __launch_bounds__(256, 2)
sgemm_nt(const float* __restrict__ A, const float* __restrict__ B,
         float* __restrict__ C, const float* __restrict__ bias,
         int M, int N, int K)
{
    __shared__ float As[2][BK][BM];
    __shared__ float Bs[2][BK][BN];

    const int tid = threadIdx.x;
    const int m0 = blockIdx.y * BM;
    const int n0 = blockIdx.x * BN;

    const int lr = tid >> 1;          // 0..127
    const int lc = (tid & 1) * 4;     // 0 or 4

    const float* Ag = A + (size_t)(m0 + lr) * K + lc;
    const float* Bg = B + (size_t)(n0 + lr) * K + lc;

    // preload tile 0
    float4 a = *(const float4*)Ag;
    float4 b = *(const float4*)Bg;
    As[0][lc+0][lr] = a.x; As[0][lc+1][lr] = a.y;
    As[0][lc+2][lr] = a.z; As[0][lc+3][lr] = a.w;
    Bs[0][lc+0][lr] = b.x; Bs[0][lc+1][lr] = b.y;
    Bs[0][lc+2][lr] = b.z; Bs[0][lc+3][lr] = b.w;
    __syncthreads();

    const int tx = tid & 15;
    const int ty = tid >> 4;

    float acc[8][8];
#pragma unroll
    for (int i = 0; i < 8; i++)
#pragma unroll
        for (int j = 0; j < 8; j++) acc[i][j] = 0.f;

    const int ntiles = K / BK;
    for (int kt = 0; kt < ntiles; kt++) {
        const int cur = kt & 1;
        float4 an, bn;
        const bool more = (kt + 1 < ntiles);
        if (more) {
            an = *(const float4*)(Ag + (kt + 1) * BK);
            bn = *(const float4*)(Bg + (kt + 1) * BK);
        }
#pragma unroll
        for (int k = 0; k < BK; k++) {
            float ar[8], br[8];
            *(float4*)&ar[0] = *(const float4*)&As[cur][k][ty * 8];
            *(float4*)&ar[4] = *(const float4*)&As[cur][k][ty * 8 + 4];
            *(float4*)&br[0] = *(const float4*)&Bs[cur][k][tx * 8];
            *(float4*)&br[4] = *(const float4*)&Bs[cur][k][tx * 8 + 4];
#pragma unroll
            for (int i = 0; i < 8; i++)
#pragma unroll
                for (int j = 0; j < 8; j++)
                    acc[i][j] += ar[i] * br[j];
        }
        if (more) {
            const int nxt = cur ^ 1;
            As[nxt][lc+0][lr] = an.x; As[nxt][lc+1][lr] = an.y;
            As[nxt][lc+2][lr] = an.z; As[nxt][lc+3][lr] = an.w;
            Bs[nxt][lc+0][lr] = bn.x; Bs[nxt][lc+1][lr] = bn.y;
            Bs[nxt][lc+2][lr] = bn.z; Bs[nxt][lc+3][lr] = bn.w;
            __syncthreads();
        }
    }

    // epilogue
    float bv[8];
    if (bias) {
#pragma unroll
        for (int j = 0; j < 8; j++) bv[j] = bias[n0 + tx * 8 + j];
    } else {
#pragma unroll
        for (int j = 0; j < 8; j++) bv[j] = 0.f;
    }
#pragma unroll
    for (int i = 0; i < 8; i++) {
        const int row = m0 + ty * 8 + i;
        float* Cp = C + (size_t)row * N + n0 + tx * 8;
        float4 c0, c1;
        c0.x = acc[i][0] + bv[0]; c0.y = acc[i][1] + bv[1];
        c0.z = acc[i][2] + bv[2]; c0.w = acc[i][3] + bv[3];
        c1.x = acc[i][4] + bv[4]; c1.y = acc[i][5] + bv[5];
        c1.z = acc[i][6] + bv[6]; c1.w = acc[i][7] + bv[7];
        *(float4*)Cp       = c0;
        *(float4*)(Cp + 4) = c1;
    }
}

// ---------------------------------------------------------------------------
// Attention kernel: one block (256 thr) per (sequence n, head).
// n = b*576 + h*32 + w ; token(t) = b*18432 + t*576 + (n % 576)
// Loads Q,K,V (32x64 each) to smem, applies RoPE to Q,K, computes causal
// softmax(QK^T/8) @ V, writes to g_att[token][head*64+d].
// ---------------------------------------------------------------------------
__global__ void __launch_bounds__(256)
attn_kernel(const float* __restrict__ qkv, float* __restrict__ att)
{
    const int blk  = blockIdx.x;       // 0..18431
    const int head = blk & 15;
    const int n    = blk >> 4;
    const int b    = n / HWP;
    const int hw   = n - b * HWP;
    const size_t base_tok = (size_t)b * (TT * HWP) + hw;

    __shared__ float Qs[32][65];
    __shared__ float Ks[32][65];
    __shared__ float Vs[32][64];
    __shared__ float Ss[32][33];

    const int tid = threadIdx.x;

    // ---- load Q,K,V ----
    for (int i = tid; i < 32 * 64; i += 256) {
        const int t = i >> 6, d = i & 63;
        const size_t tok = base_tok + (size_t)t * HWP;
        const float* p = qkv + tok * EQKV + head * HD + d;
        Qs[t][d] = p[0];
        Ks[t][d] = p[1024];
        Vs[t][d] = p[2048];
    }
    __syncthreads();

    // ---- RoPE on Q and K (first 32 dims, interleaved pairs) ----
    for (int i = tid; i < 2 * 32 * 16; i += 256) {
        const int mat = i >> 9;
        const int rem = i & 511;
        const int t = rem >> 4, j = rem & 15;
        const float freq = powf(10000.0f, -(float)j / 16.0f);
        const float ang = (float)t * freq;
        const float c = cosf(ang), s = sinf(ang);
        float (*P)[65] = mat ? Ks : Qs;
        const float x0 = P[t][2 * j];
        const float x1 = P[t][2 * j + 1];
        P[t][2 * j]     = x0 * c - x1 * s;
        P[t][2 * j + 1] = x1 * c + x0 * s;
    }
    __syncthreads();

    // ---- scores S = Q K^T (2x2 per thread) ----
    const int r = tid >> 4, c = tid & 15;
    {
        float s00 = 0.f, s01 = 0.f, s10 = 0.f, s11 = 0.f;
#pragma unroll 16
        for (int d = 0; d < 64; d++) {
            const float q0 = Qs[2 * r][d],     q1 = Qs[2 * r + 1][d];
            const float k0 = Ks[2 * c][d],     k1 = Ks[2 * c + 1][d];
            s00 += q0 * k0; s01 += q0 * k1;
            s10 += q1 * k0; s11 += q1 * k1;
        }
        Ss[2 * r][2 * c]         = s00;
        Ss[2 * r][2 * c + 1]     = s01;
        Ss[2 * r + 1][2 * c]     = s10;
        Ss[2 * r + 1][2 * c + 1] = s11;
    }
    __syncthreads();

    // ---- causal softmax: warp per 4 rows, lane = key column ----
    const int warp = tid >> 5, lane = tid & 31;
    const float scale = 0.125f;                     // 1/sqrt(64)
#pragma unroll
    for (int qi = 0; qi < 4; qi++) {
        const int q = warp * 4 + qi;
        float s = (lane <= q) ? Ss[q][lane] * scale : -INFINITY;
        float m = s;
#pragma unroll
        for (int o = 16; o > 0; o >>= 1)
            m = fmaxf(m, __shfl_xor_sync(0xffffffffu, m, o));
        const float e = expf(s - m);
        float sum = e;
#pragma unroll
        for (int o = 16; o > 0; o >>= 1)
            sum += __shfl_xor_sync(0xffffffffu, sum, o);
        Ss[q][lane] = e / sum;
    }
    __syncthreads();

    // ---- O = P @ V : thread does rows {2r,2r+1}, cols 4c..4c+3 ----
    float o0[4] = {0.f, 0.f, 0.f, 0.f};
    float o1[4] = {0.f, 0.f, 0.f, 0.f};
#pragma unroll 8
    for (int k = 0; k < 32; k++) {
        const float p0 = Ss[2 * r][k];
        const float p1 = Ss[2 * r + 1][k];
#pragma unroll
        for (int j = 0; j < 4; j++) {
            const float v = Vs[k][4 * c + j];
            o0[j] += p0 * v;
            o1[j] += p1 * v;
        }
    }
#pragma unroll
    for (int i = 0; i < 2; i++) {
        const int t = 2 * r + i;
        const size_t tok = base_tok + (size_t)t * HWP;
        float* dst = att + tok * EO + head * HD + 4 * c;
        const float* src = i ? o1 : o0;
        dst[0] = src[0]; dst[1] = src[1]; dst[2] = src[2]; dst[3] = src[3];
    }
}

// ---------------------------------------------------------------------------
extern "C" void kernel_launch(void* const* d_in, const int* in_sizes, int n_in,
                              void* d_out, int out_size)
{
    const float* x     = (const float*)d_in[0];
    const float* w_qkv = (const float*)d_in[1];
    const float* w_out = (const float*)d_in[2];
    const float* b_out = (const float*)d_in[3];
    float* out = (float*)d_out;

    void* qkv_p = nullptr;
    void* att_p = nullptr;
    cudaGetSymbolAddress(&qkv_p, g_qkv);
    cudaGetSymbolAddress(&att_p, g_att);
    float* qkv = (float*)qkv_p;
    float* att = (float*)att_p;

    // 1) QKV projection: [36864,1024] x [3072,1024]^T -> [36864,3072]
    {
        dim3 grid(EQKV / BN, MTOK / BM);
        sgemm_nt<<<grid, 256>>>(x, w_qkv, qkv, nullptr, MTOK, EQKV, DIM);
    }
    // 2) RoPE + causal attention per (seq, head)
    {
        const int nblk = (BB * HWP) * HEADS;   // 18432
        attn_kernel<<<nblk, 256>>>(qkv, att);
    }
    // 3) Output projection + bias: [36864,1024] x [1024,1024]^T -> out
    {
        dim3 grid(DIM / BN, MTOK / BM);
        sgemm_nt<<<grid, 256>>>(att, w_out, out, b_out, MTOK, DIM, DIM);
    }
}

// round 6
// speedup vs baseline: 2.7324x; 2.7324x over previous
#include <cuda_runtime.h>
#include <cuda_bf16.h>
#include <cstdint>
#include <math.h>

// Problem constants
#define BB    2
#define TT    32
#define HH    18
#define WW    32
#define DIM   1024
#define HEADS 16
#define HD    64
#define HWP   (HH*WW)            // 576
#define MTOK  (BB*TT*HWP)        // 36864 tokens
#define EQKV  (3*HEADS*HD)       // 3072
#define EO    (HEADS*HD)         // 1024

// ---------------- scratch (device globals; no allocation allowed) ----------
__device__ float          g_qkv[(size_t)MTOK * EQKV];
__device__ __nv_bfloat16  g_x_hi[(size_t)MTOK * DIM];
__device__ __nv_bfloat16  g_x_lo[(size_t)MTOK * DIM];
__device__ __nv_bfloat16  g_wqkv_hi[(size_t)EQKV * DIM];
__device__ __nv_bfloat16  g_wqkv_lo[(size_t)EQKV * DIM];
__device__ __nv_bfloat16  g_wout_hi[(size_t)DIM * DIM];
__device__ __nv_bfloat16  g_wout_lo[(size_t)DIM * DIM];
__device__ __nv_bfloat16  g_att_hi[(size_t)MTOK * EO];
__device__ __nv_bfloat16  g_att_lo[(size_t)MTOK * EO];

// ---------------- helpers ---------------------------------------------------
__device__ __forceinline__ uint32_t smem_u32(const void* p) {
    uint32_t a;
    asm("{ .reg .u64 t; cvta.to.shared.u64 t, %1; cvt.u32.u64 %0, t; }" : "=r"(a) : "l"(p));
    return a;
}

#define SWZ128(off) ((off) ^ (((off) >> 3) & 0x70))

__device__ __forceinline__ void cp16(uint32_t saddr, const void* g) {
    asm volatile("cp.async.cg.shared.global [%0], [%1], 16;" :: "r"(saddr), "l"(g));
}
#define CP_COMMIT() asm volatile("cp.async.commit_group;" ::: "memory")
#define CP_WAIT0()  asm volatile("cp.async.wait_group 0;" ::: "memory")
#define CP_WAIT1()  asm volatile("cp.async.wait_group 1;" ::: "memory")

__device__ __forceinline__ void ldm_x4(uint32_t* r, uint32_t addr) {
    asm volatile("ldmatrix.sync.aligned.m8n8.x4.shared.b16 {%0,%1,%2,%3}, [%4];"
                 : "=r"(r[0]), "=r"(r[1]), "=r"(r[2]), "=r"(r[3]) : "r"(addr));
}

__device__ __forceinline__ void mma16816(float* d, const uint32_t* a, const uint32_t* b) {
    asm volatile("mma.sync.aligned.m16n8k16.row.col.f32.bf16.bf16.f32 "
                 "{%0,%1,%2,%3}, {%4,%5,%6,%7}, {%8,%9}, {%0,%1,%2,%3};"
                 : "+f"(d[0]), "+f"(d[1]), "+f"(d[2]), "+f"(d[3])
                 : "r"(a[0]), "r"(a[1]), "r"(a[2]), "r"(a[3]), "r"(b[0]), "r"(b[1]));
}

// ---------------------------------------------------------------------------
// split: fp32 -> bf16 hi + bf16 lo (residual)
// ---------------------------------------------------------------------------
__global__ void __launch_bounds__(256)
split_kernel(const float* __restrict__ in, __nv_bfloat16* __restrict__ hi,
             __nv_bfloat16* __restrict__ lo, int n4)
{
    int i = blockIdx.x * 256 + threadIdx.x;
    if (i >= n4) return;
    float4 v = ((const float4*)in)[i];
    __nv_bfloat16 h[4], l[4];
    float f[4] = {v.x, v.y, v.z, v.w};
#pragma unroll
    for (int j = 0; j < 4; j++) {
        h[j] = __float2bfloat16(f[j]);
        l[j] = __float2bfloat16(f[j] - __bfloat162float(h[j]));
    }
    ((uint64_t*)hi)[i] = *(const uint64_t*)h;
    ((uint64_t*)lo)[i] = *(const uint64_t*)l;
}

// ---------------------------------------------------------------------------
// bf16 3-term split GEMM on mma.sync (HMMA): C[M,N] = A x B^T (+bias)
// CTA tile 128x128, BK=64, 2-stage cp.async pipeline, 8 warps (2m x 4n),
// warp tile 64x32. Segments: (Ahi,Bhi), (Alo,Bhi), (Ahi,Blo).
// ---------------------------------------------------------------------------
#define GBK      64
#define STAGE_A  16384                 // 128*64*2 bytes
#define STAGE_SZ 32768                 // A + B
#define GSMEM_SZ (2 * STAGE_SZ)       // 65536

__device__ __forceinline__ void fill_chunk(
    int cc, int kchunks, uint32_t dst, int tid, int m0, int n0, int K,
    const __nv_bfloat16* __restrict__ Ahi, const __nv_bfloat16* __restrict__ Alo,
    const __nv_bfloat16* __restrict__ Bhi, const __nv_bfloat16* __restrict__ Blo)
{
    const int seg = cc / kchunks;
    const int kk  = (cc - seg * kchunks) * GBK;
    const __nv_bfloat16* A = (seg == 1) ? Alo : Ahi;
    const __nv_bfloat16* B = (seg == 2) ? Blo : Bhi;
#pragma unroll
    for (int i = 0; i < 4; i++) {
        const int u = tid + i * 256;
        const int row = u >> 3, c16 = u & 7;
        const uint32_t so = SWZ128((uint32_t)(row * 128 + c16 * 16));
        cp16(dst + so,           A + (size_t)(m0 + row) * K + kk + c16 * 8);
        cp16(dst + STAGE_A + so, B + (size_t)(n0 + row) * K + kk + c16 * 8);
    }
}

__global__ void __launch_bounds__(256, 2)
gemm_bf16x3(const __nv_bfloat16* __restrict__ Ahi, const __nv_bfloat16* __restrict__ Alo,
            const __nv_bfloat16* __restrict__ Bhi, const __nv_bfloat16* __restrict__ Blo,
            float* __restrict__ C, const float* __restrict__ bias, int N, int K)
{
    extern __shared__ char smem[];
    const uint32_t sb = smem_u32(smem);
    const int tid = threadIdx.x;
    const int m0 = blockIdx.y * 128;
    const int n0 = blockIdx.x * 128;
    const int lane = tid & 31;
    const int warp = tid >> 5;
    const int warp_m = warp >> 2;      // 0..1
    const int warp_n = warp & 3;       // 0..3

    float acc[4][4][4];
#pragma unroll
    for (int a = 0; a < 4; a++)
#pragma unroll
        for (int b = 0; b < 4; b++)
#pragma unroll
            for (int c = 0; c < 4; c++) acc[a][b][c] = 0.f;

    const int kchunks = K / GBK;       // 16
    const int total = 3 * kchunks;     // 48

    fill_chunk(0, kchunks, sb, tid, m0, n0, K, Ahi, Alo, Bhi, Blo);
    CP_COMMIT();

    // per-thread ldmatrix address components (byte offsets within tile, pre-swizzle)
    const uint32_t a_row_half = (uint32_t)(lane & 15);         // row within 16
    const uint32_t a_koff     = (uint32_t)((lane >> 4) << 4);  // 0 or 16 bytes
    const uint32_t b_row_half = (uint32_t)(((lane >> 4) << 3) + (lane & 7));
    const uint32_t b_koff     = (uint32_t)(((lane >> 3) & 1) << 4);

    for (int cc = 0; cc < total; cc++) {
        const uint32_t abase = sb + (uint32_t)(cc & 1) * STAGE_SZ;
        const uint32_t bbase = abase + STAGE_A;
        if (cc + 1 < total) {
            fill_chunk(cc + 1, kchunks, sb + (uint32_t)((cc + 1) & 1) * STAGE_SZ,
                       tid, m0, n0, K, Ahi, Alo, Bhi, Blo);
            CP_COMMIT();
            CP_WAIT1();
        } else {
            CP_WAIT0();
        }
        __syncthreads();

#pragma unroll
        for (int ks = 0; ks < 4; ks++) {
            uint32_t af[4][4];
#pragma unroll
            for (int mt = 0; mt < 4; mt++) {
                const uint32_t row = (uint32_t)(warp_m * 64 + mt * 16) + a_row_half;
                const uint32_t off = row * 128 + (uint32_t)(ks * 32) + a_koff;
                ldm_x4(af[mt], abase + SWZ128(off));
            }
            uint32_t bf[2][4];
#pragma unroll
            for (int nt2 = 0; nt2 < 2; nt2++) {
                const uint32_t row = (uint32_t)(warp_n * 32 + nt2 * 16) + b_row_half;
                const uint32_t off = row * 128 + (uint32_t)(ks * 32) + b_koff;
                ldm_x4(bf[nt2], bbase + SWZ128(off));
            }
#pragma unroll
            for (int mt = 0; mt < 4; mt++)
#pragma unroll
                for (int nt = 0; nt < 4; nt++)
                    mma16816(acc[mt][nt], af[mt], &bf[nt >> 1][(nt & 1) * 2]);
        }
        __syncthreads();
    }

    // epilogue
    const int ln4 = lane >> 2;
    const int lc2 = (lane & 3) * 2;
#pragma unroll
    for (int mt = 0; mt < 4; mt++) {
        const int r0 = m0 + warp_m * 64 + mt * 16 + ln4;
#pragma unroll
        for (int nt = 0; nt < 4; nt++) {
            const int col = n0 + warp_n * 32 + nt * 8 + lc2;
            float bx = 0.f, by = 0.f;
            if (bias) { bx = bias[col]; by = bias[col + 1]; }
            float2 v0 = make_float2(acc[mt][nt][0] + bx, acc[mt][nt][1] + by);
            float2 v1 = make_float2(acc[mt][nt][2] + bx, acc[mt][nt][3] + by);
            *(float2*)(C + (size_t)r0 * N + col)       = v0;
            *(float2*)(C + (size_t)(r0 + 8) * N + col) = v1;
        }
    }
}

// ---------------------------------------------------------------------------
// Attention: one block per (sequence, head). Writes bf16 hi/lo split output.
// ---------------------------------------------------------------------------
__global__ void __launch_bounds__(256)
attn_kernel(const float* __restrict__ qkv,
            __nv_bfloat16* __restrict__ att_hi, __nv_bfloat16* __restrict__ att_lo)
{
    const int blk  = blockIdx.x;
    const int head = blk & 15;
    const int n    = blk >> 4;
    const int b    = n / HWP;
    const int hw   = n - b * HWP;
    const size_t base_tok = (size_t)b * (TT * HWP) + hw;

    __shared__ float Qs[32][65];
    __shared__ float Ks[32][65];
    __shared__ float Vs[32][64];
    __shared__ float Ss[32][33];

    const int tid = threadIdx.x;

    for (int i = tid; i < 32 * 64; i += 256) {
        const int t = i >> 6, d = i & 63;
        const size_t tok = base_tok + (size_t)t * HWP;
        const float* p = qkv + tok * EQKV + head * HD + d;
        Qs[t][d] = p[0];
        Ks[t][d] = p[1024];
        Vs[t][d] = p[2048];
    }
    __syncthreads();

    for (int i = tid; i < 2 * 32 * 16; i += 256) {
        const int mat = i >> 9;
        const int rem = i & 511;
        const int t = rem >> 4, j = rem & 15;
        const float freq = powf(10000.0f, -(float)j / 16.0f);
        const float ang = (float)t * freq;
        const float c = cosf(ang), s = sinf(ang);
        float (*P)[65] = mat ? Ks : Qs;
        const float x0 = P[t][2 * j];
        const float x1 = P[t][2 * j + 1];
        P[t][2 * j]     = x0 * c - x1 * s;
        P[t][2 * j + 1] = x1 * c + x0 * s;
    }
    __syncthreads();

    const int r = tid >> 4, c = tid & 15;
    {
        float s00 = 0.f, s01 = 0.f, s10 = 0.f, s11 = 0.f;
#pragma unroll 16
        for (int d = 0; d < 64; d++) {
            const float q0 = Qs[2 * r][d],     q1 = Qs[2 * r + 1][d];
            const float k0 = Ks[2 * c][d],     k1 = Ks[2 * c + 1][d];
            s00 += q0 * k0; s01 += q0 * k1;
            s10 += q1 * k0; s11 += q1 * k1;
        }
        Ss[2 * r][2 * c]         = s00;
        Ss[2 * r][2 * c + 1]     = s01;
        Ss[2 * r + 1][2 * c]     = s10;
        Ss[2 * r + 1][2 * c + 1] = s11;
    }
    __syncthreads();

    const int warp = tid >> 5, lane = tid & 31;
    const float scale = 0.125f;
#pragma unroll
    for (int qi = 0; qi < 4; qi++) {
        const int q = warp * 4 + qi;
        float s = (lane <= q) ? Ss[q][lane] * scale : -INFINITY;
        float m = s;
#pragma unroll
        for (int o = 16; o > 0; o >>= 1)
            m = fmaxf(m, __shfl_xor_sync(0xffffffffu, m, o));
        const float e = expf(s - m);
        float sum = e;
#pragma unroll
        for (int o = 16; o > 0; o >>= 1)
            sum += __shfl_xor_sync(0xffffffffu, sum, o);
        Ss[q][lane] = e / sum;
    }
    __syncthreads();

    float o0[4] = {0.f, 0.f, 0.f, 0.f};
    float o1[4] = {0.f, 0.f, 0.f, 0.f};
#pragma unroll 8
    for (int k = 0; k < 32; k++) {
        const float p0 = Ss[2 * r][k];
        const float p1 = Ss[2 * r + 1][k];
#pragma unroll
        for (int j = 0; j < 4; j++) {
            const float v = Vs[k][4 * c + j];
            o0[j] += p0 * v;
            o1[j] += p1 * v;
        }
    }
#pragma unroll
    for (int i = 0; i < 2; i++) {
        const int t = 2 * r + i;
        const size_t tok = base_tok + (size_t)t * HWP;
        const size_t base = tok * EO + head * HD + 4 * c;
        const float* src = i ? o1 : o0;
        __nv_bfloat16 h[4], l[4];
#pragma unroll
        for (int j = 0; j < 4; j++) {
            h[j] = __float2bfloat16(src[j]);
            l[j] = __float2bfloat16(src[j] - __bfloat162float(h[j]));
        }
        *(uint64_t*)(att_hi + base) = *(const uint64_t*)h;
        *(uint64_t*)(att_lo + base) = *(const uint64_t*)l;
    }
}

// ---------------------------------------------------------------------------
extern "C" void kernel_launch(void* const* d_in, const int* in_sizes, int n_in,
                              void* d_out, int out_size)
{
    const float* x     = (const float*)d_in[0];
    const float* w_qkv = (const float*)d_in[1];
    const float* w_out = (const float*)d_in[2];
    const float* b_out = (const float*)d_in[3];
    float* out = (float*)d_out;

    void *qkv_p, *xh_p, *xl_p, *wqh_p, *wql_p, *woh_p, *wol_p, *ah_p, *al_p;
    cudaGetSymbolAddress(&qkv_p, g_qkv);
    cudaGetSymbolAddress(&xh_p,  g_x_hi);    cudaGetSymbolAddress(&xl_p,  g_x_lo);
    cudaGetSymbolAddress(&wqh_p, g_wqkv_hi); cudaGetSymbolAddress(&wql_p, g_wqkv_lo);
    cudaGetSymbolAddress(&woh_p, g_wout_hi); cudaGetSymbolAddress(&wol_p, g_wout_lo);
    cudaGetSymbolAddress(&ah_p,  g_att_hi);  cudaGetSymbolAddress(&al_p,  g_att_lo);

    float* qkv = (float*)qkv_p;
    __nv_bfloat16 *xh = (__nv_bfloat16*)xh_p, *xl = (__nv_bfloat16*)xl_p;
    __nv_bfloat16 *wqh = (__nv_bfloat16*)wqh_p, *wql = (__nv_bfloat16*)wql_p;
    __nv_bfloat16 *woh = (__nv_bfloat16*)woh_p, *wol = (__nv_bfloat16*)wol_p;
    __nv_bfloat16 *ah = (__nv_bfloat16*)ah_p, *al = (__nv_bfloat16*)al_p;

    cudaFuncSetAttribute(gemm_bf16x3, cudaFuncAttributeMaxDynamicSharedMemorySize, GSMEM_SZ);

    // 0) split inputs into bf16 hi/lo
    {
        int n4 = (MTOK * DIM) / 4;
        split_kernel<<<(n4 + 255) / 256, 256>>>(x, xh, xl, n4);
        n4 = (EQKV * DIM) / 4;
        split_kernel<<<(n4 + 255) / 256, 256>>>(w_qkv, wqh, wql, n4);
        n4 = (DIM * DIM) / 4;
        split_kernel<<<(n4 + 255) / 256, 256>>>(w_out, woh, wol, n4);
    }
    // 1) QKV projection: [36864,1024] x [3072,1024]^T
    {
        dim3 grid(EQKV / 128, MTOK / 128);
        gemm_bf16x3<<<grid, 256, GSMEM_SZ>>>(xh, xl, wqh, wql, qkv, nullptr, EQKV, DIM);
    }
    // 2) RoPE + causal attention, writes split bf16 att
    {
        attn_kernel<<<(BB * HWP) * HEADS, 256>>>(qkv, ah, al);
    }
    // 3) Output projection + bias
    {
        dim3 grid(DIM / 128, MTOK / 128);
        gemm_bf16x3<<<grid, 256, GSMEM_SZ>>>(ah, al, woh, wol, out, b_out, DIM, DIM);
    }
}

// round 7
// speedup vs baseline: 2.8472x; 1.0420x over previous
#include <cuda_runtime.h>
#include <cuda_bf16.h>
#include <cstdint>
#include <math.h>

// Problem constants
#define BB    2
#define TT    32
#define HH    18
#define WW    32
#define DIM   1024
#define HEADS 16
#define HD    64
#define HWP   (HH*WW)            // 576
#define MTOK  (BB*TT*HWP)        // 36864 tokens
#define EQKV  (3*HEADS*HD)       // 3072
#define EO    (HEADS*HD)         // 1024

// ---------------- scratch (device globals; no allocation allowed) ----------
__device__ float          g_qkv[(size_t)MTOK * EQKV];
__device__ __nv_bfloat16  g_x_hi[(size_t)MTOK * DIM];
__device__ __nv_bfloat16  g_x_lo[(size_t)MTOK * DIM];
__device__ __nv_bfloat16  g_wqkv_hi[(size_t)EQKV * DIM];
__device__ __nv_bfloat16  g_wqkv_lo[(size_t)EQKV * DIM];
__device__ __nv_bfloat16  g_wout_hi[(size_t)DIM * DIM];
__device__ __nv_bfloat16  g_wout_lo[(size_t)DIM * DIM];
__device__ __nv_bfloat16  g_att_hi[(size_t)MTOK * EO];
__device__ __nv_bfloat16  g_att_lo[(size_t)MTOK * EO];

// ---------------- helpers ---------------------------------------------------
__device__ __forceinline__ uint32_t smem_u32(const void* p) {
    uint32_t a;
    asm("{ .reg .u64 t; cvta.to.shared.u64 t, %1; cvt.u32.u64 %0, t; }" : "=r"(a) : "l"(p));
    return a;
}

#define SWZ128(off) ((off) ^ (((off) >> 3) & 0x70))

__device__ __forceinline__ void cp16(uint32_t saddr, const void* g) {
    asm volatile("cp.async.cg.shared.global [%0], [%1], 16;" :: "r"(saddr), "l"(g));
}
#define CP_COMMIT() asm volatile("cp.async.commit_group;" ::: "memory")
#define CP_WAIT0()  asm volatile("cp.async.wait_group 0;" ::: "memory")
#define CP_WAIT1()  asm volatile("cp.async.wait_group 1;" ::: "memory")

__device__ __forceinline__ void ldm_x4(uint32_t* r, uint32_t addr) {
    asm volatile("ldmatrix.sync.aligned.m8n8.x4.shared.b16 {%0,%1,%2,%3}, [%4];"
                 : "=r"(r[0]), "=r"(r[1]), "=r"(r[2]), "=r"(r[3]) : "r"(addr));
}

__device__ __forceinline__ void mma16816(float* d, const uint32_t* a, const uint32_t* b) {
    asm volatile("mma.sync.aligned.m16n8k16.row.col.f32.bf16.bf16.f32 "
                 "{%0,%1,%2,%3}, {%4,%5,%6,%7}, {%8,%9}, {%0,%1,%2,%3};"
                 : "+f"(d[0]), "+f"(d[1]), "+f"(d[2]), "+f"(d[3])
                 : "r"(a[0]), "r"(a[1]), "r"(a[2]), "r"(a[3]), "r"(b[0]), "r"(b[1]));
}

// ---------------------------------------------------------------------------
// split: fp32 -> bf16 hi + bf16 lo (residual)
// ---------------------------------------------------------------------------
__global__ void __launch_bounds__(256)
split_kernel(const float* __restrict__ in, __nv_bfloat16* __restrict__ hi,
             __nv_bfloat16* __restrict__ lo, int n4)
{
    int i = blockIdx.x * 256 + threadIdx.x;
    if (i >= n4) return;
    float4 v = ((const float4*)in)[i];
    __nv_bfloat16 h[4], l[4];
    float f[4] = {v.x, v.y, v.z, v.w};
#pragma unroll
    for (int j = 0; j < 4; j++) {
        h[j] = __float2bfloat16(f[j]);
        l[j] = __float2bfloat16(f[j] - __bfloat162float(h[j]));
    }
    ((uint64_t*)hi)[i] = *(const uint64_t*)h;
    ((uint64_t*)lo)[i] = *(const uint64_t*)l;
}

// ---------------------------------------------------------------------------
// FUSED bf16 3-term split GEMM on mma.sync: C[M,N] = A x B^T (+bias)
// CTA tile 128x128, BK=64. Per k-chunk, ONE 64KB stage holds Ahi|Alo|Bhi|Blo;
// all three terms (ah*bh + al*bh + ah*bl) are computed per chunk -> 3x math
// per barrier and 1/3 the tile traffic vs segmented. 3-stage cp.async ring.
// 8 warps (2m x 4n), warp tile 64x32.
// ---------------------------------------------------------------------------
#define GBK      64
#define SUB_A_LO 16384
#define SUB_B_HI 32768
#define SUB_B_LO 49152
#define STAGE_SZ 65536
#define NSTAGE   3
#define GSMEM_SZ (NSTAGE * STAGE_SZ)   // 196608

__device__ __forceinline__ void fill_chunk(
    int cc, uint32_t dst, int tid, int m0, int n0, int K,
    const __nv_bfloat16* __restrict__ Ahi, const __nv_bfloat16* __restrict__ Alo,
    const __nv_bfloat16* __restrict__ Bhi, const __nv_bfloat16* __restrict__ Blo)
{
    const int kk = cc * GBK;
#pragma unroll
    for (int i = 0; i < 4; i++) {
        const int u = tid + i * 256;
        const int row = u >> 3, c16 = u & 7;
        const uint32_t so = SWZ128((uint32_t)(row * 128 + c16 * 16));
        const size_t aoff = (size_t)(m0 + row) * K + kk + c16 * 8;
        const size_t boff = (size_t)(n0 + row) * K + kk + c16 * 8;
        cp16(dst + so,            Ahi + aoff);
        cp16(dst + SUB_A_LO + so, Alo + aoff);
        cp16(dst + SUB_B_HI + so, Bhi + boff);
        cp16(dst + SUB_B_LO + so, Blo + boff);
    }
}

__global__ void __launch_bounds__(256, 1)
gemm_bf16x3(const __nv_bfloat16* __restrict__ Ahi, const __nv_bfloat16* __restrict__ Alo,
            const __nv_bfloat16* __restrict__ Bhi, const __nv_bfloat16* __restrict__ Blo,
            float* __restrict__ C, const float* __restrict__ bias, int N, int K)
{
    extern __shared__ char smem[];
    const uint32_t sb = smem_u32(smem);
    const int tid = threadIdx.x;
    const int m0 = blockIdx.y * 128;
    const int n0 = blockIdx.x * 128;
    const int lane = tid & 31;
    const int warp = tid >> 5;
    const int warp_m = warp >> 2;      // 0..1
    const int warp_n = warp & 3;       // 0..3

    float acc[4][4][4];
#pragma unroll
    for (int a = 0; a < 4; a++)
#pragma unroll
        for (int b = 0; b < 4; b++)
#pragma unroll
            for (int c = 0; c < 4; c++) acc[a][b][c] = 0.f;

    const int kchunks = K / GBK;       // 16

    fill_chunk(0, sb, tid, m0, n0, K, Ahi, Alo, Bhi, Blo);
    CP_COMMIT();
    fill_chunk(1, sb + STAGE_SZ, tid, m0, n0, K, Ahi, Alo, Bhi, Blo);
    CP_COMMIT();

    // per-thread ldmatrix address components (byte offsets within tile, pre-swizzle)
    const uint32_t a_row_half = (uint32_t)(lane & 15);         // row within 16
    const uint32_t a_koff     = (uint32_t)((lane >> 4) << 4);  // 0 or 16 bytes
    const uint32_t b_row_half = (uint32_t)(((lane >> 4) << 3) + (lane & 7));
    const uint32_t b_koff     = (uint32_t)(((lane >> 3) & 1) << 4);

    for (int cc = 0; cc < kchunks; cc++) {
        if (cc + 1 < kchunks) { CP_WAIT1(); } else { CP_WAIT0(); }
        __syncthreads();
        if (cc + 2 < kchunks) {
            fill_chunk(cc + 2, sb + (uint32_t)((cc + 2) % NSTAGE) * STAGE_SZ,
                       tid, m0, n0, K, Ahi, Alo, Bhi, Blo);
            CP_COMMIT();
        }
        const uint32_t st = sb + (uint32_t)(cc % NSTAGE) * STAGE_SZ;

#pragma unroll
        for (int ks = 0; ks < 4; ks++) {
            uint32_t ah[4][4], al[4][4];
#pragma unroll
            for (int mt = 0; mt < 4; mt++) {
                const uint32_t row = (uint32_t)(warp_m * 64 + mt * 16) + a_row_half;
                const uint32_t so = SWZ128(row * 128 + (uint32_t)(ks * 32) + a_koff);
                ldm_x4(ah[mt], st + so);
                ldm_x4(al[mt], st + SUB_A_LO + so);
            }
            uint32_t bh[2][4], bl[2][4];
#pragma unroll
            for (int nt2 = 0; nt2 < 2; nt2++) {
                const uint32_t row = (uint32_t)(warp_n * 32 + nt2 * 16) + b_row_half;
                const uint32_t so = SWZ128(row * 128 + (uint32_t)(ks * 32) + b_koff);
                ldm_x4(bh[nt2], st + SUB_B_HI + so);
                ldm_x4(bl[nt2], st + SUB_B_LO + so);
            }
#pragma unroll
            for (int mt = 0; mt < 4; mt++)
#pragma unroll
                for (int nt = 0; nt < 4; nt++) {
                    const uint32_t* bph = &bh[nt >> 1][(nt & 1) * 2];
                    const uint32_t* bpl = &bl[nt >> 1][(nt & 1) * 2];
                    mma16816(acc[mt][nt], ah[mt], bph);
                    mma16816(acc[mt][nt], al[mt], bph);
                    mma16816(acc[mt][nt], ah[mt], bpl);
                }
        }
    }

    __syncthreads();

    // epilogue
    const int ln4 = lane >> 2;
    const int lc2 = (lane & 3) * 2;
#pragma unroll
    for (int mt = 0; mt < 4; mt++) {
        const int r0 = m0 + warp_m * 64 + mt * 16 + ln4;
#pragma unroll
        for (int nt = 0; nt < 4; nt++) {
            const int col = n0 + warp_n * 32 + nt * 8 + lc2;
            float bx = 0.f, by = 0.f;
            if (bias) { bx = bias[col]; by = bias[col + 1]; }
            float2 v0 = make_float2(acc[mt][nt][0] + bx, acc[mt][nt][1] + by);
            float2 v1 = make_float2(acc[mt][nt][2] + bx, acc[mt][nt][3] + by);
            *(float2*)(C + (size_t)r0 * N + col)       = v0;
            *(float2*)(C + (size_t)(r0 + 8) * N + col) = v1;
        }
    }
}

// ---------------------------------------------------------------------------
// Attention: one block per (sequence, head). Writes bf16 hi/lo split output.
// ---------------------------------------------------------------------------
__global__ void __launch_bounds__(256)
attn_kernel(const float* __restrict__ qkv,
            __nv_bfloat16* __restrict__ att_hi, __nv_bfloat16* __restrict__ att_lo)
{
    const int blk  = blockIdx.x;
    const int head = blk & 15;
    const int n    = blk >> 4;
    const int b    = n / HWP;
    const int hw   = n - b * HWP;
    const size_t base_tok = (size_t)b * (TT * HWP) + hw;

    __shared__ float Qs[32][65];
    __shared__ float Ks[32][65];
    __shared__ float Vs[32][64];
    __shared__ float Ss[32][33];

    const int tid = threadIdx.x;

    for (int i = tid; i < 32 * 64; i += 256) {
        const int t = i >> 6, d = i & 63;
        const size_t tok = base_tok + (size_t)t * HWP;
        const float* p = qkv + tok * EQKV + head * HD + d;
        Qs[t][d] = p[0];
        Ks[t][d] = p[1024];
        Vs[t][d] = p[2048];
    }
    __syncthreads();

    for (int i = tid; i < 2 * 32 * 16; i += 256) {
        const int mat = i >> 9;
        const int rem = i & 511;
        const int t = rem >> 4, j = rem & 15;
        const float freq = powf(10000.0f, -(float)j / 16.0f);
        const float ang = (float)t * freq;
        const float c = cosf(ang), s = sinf(ang);
        float (*P)[65] = mat ? Ks : Qs;
        const float x0 = P[t][2 * j];
        const float x1 = P[t][2 * j + 1];
        P[t][2 * j]     = x0 * c - x1 * s;
        P[t][2 * j + 1] = x1 * c + x0 * s;
    }
    __syncthreads();

    const int r = tid >> 4, c = tid & 15;
    {
        float s00 = 0.f, s01 = 0.f, s10 = 0.f, s11 = 0.f;
#pragma unroll 16
        for (int d = 0; d < 64; d++) {
            const float q0 = Qs[2 * r][d],     q1 = Qs[2 * r + 1][d];
            const float k0 = Ks[2 * c][d],     k1 = Ks[2 * c + 1][d];
            s00 += q0 * k0; s01 += q0 * k1;
            s10 += q1 * k0; s11 += q1 * k1;
        }
        Ss[2 * r][2 * c]         = s00;
        Ss[2 * r][2 * c + 1]     = s01;
        Ss[2 * r + 1][2 * c]     = s10;
        Ss[2 * r + 1][2 * c + 1] = s11;
    }
    __syncthreads();

    const int warp = tid >> 5, lane = tid & 31;
    const float scale = 0.125f;
#pragma unroll
    for (int qi = 0; qi < 4; qi++) {
        const int q = warp * 4 + qi;
        float s = (lane <= q) ? Ss[q][lane] * scale : -INFINITY;
        float m = s;
#pragma unroll
        for (int o = 16; o > 0; o >>= 1)
            m = fmaxf(m, __shfl_xor_sync(0xffffffffu, m, o));
        const float e = expf(s - m);
        float sum = e;
#pragma unroll
        for (int o = 16; o > 0; o >>= 1)
            sum += __shfl_xor_sync(0xffffffffu, sum, o);
        Ss[q][lane] = e / sum;
    }
    __syncthreads();

    float o0[4] = {0.f, 0.f, 0.f, 0.f};
    float o1[4] = {0.f, 0.f, 0.f, 0.f};
#pragma unroll 8
    for (int k = 0; k < 32; k++) {
        const float p0 = Ss[2 * r][k];
        const float p1 = Ss[2 * r + 1][k];
#pragma unroll
        for (int j = 0; j < 4; j++) {
            const float v = Vs[k][4 * c + j];
            o0[j] += p0 * v;
            o1[j] += p1 * v;
        }
    }
#pragma unroll
    for (int i = 0; i < 2; i++) {
        const int t = 2 * r + i;
        const size_t tok = base_tok + (size_t)t * HWP;
        const size_t base = tok * EO + head * HD + 4 * c;
        const float* src = i ? o1 : o0;
        __nv_bfloat16 h[4], l[4];
#pragma unroll
        for (int j = 0; j < 4; j++) {
            h[j] = __float2bfloat16(src[j]);
            l[j] = __float2bfloat16(src[j] - __bfloat162float(h[j]));
        }
        *(uint64_t*)(att_hi + base) = *(const uint64_t*)h;
        *(uint64_t*)(att_lo + base) = *(const uint64_t*)l;
    }
}

// ---------------------------------------------------------------------------
extern "C" void kernel_launch(void* const* d_in, const int* in_sizes, int n_in,
                              void* d_out, int out_size)
{
    const float* x     = (const float*)d_in[0];
    const float* w_qkv = (const float*)d_in[1];
    const float* w_out = (const float*)d_in[2];
    const float* b_out = (const float*)d_in[3];
    float* out = (float*)d_out;

    void *qkv_p, *xh_p, *xl_p, *wqh_p, *wql_p, *woh_p, *wol_p, *ah_p, *al_p;
    cudaGetSymbolAddress(&qkv_p, g_qkv);
    cudaGetSymbolAddress(&xh_p,  g_x_hi);    cudaGetSymbolAddress(&xl_p,  g_x_lo);
    cudaGetSymbolAddress(&wqh_p, g_wqkv_hi); cudaGetSymbolAddress(&wql_p, g_wqkv_lo);
    cudaGetSymbolAddress(&woh_p, g_wout_hi); cudaGetSymbolAddress(&wol_p, g_wout_lo);
    cudaGetSymbolAddress(&ah_p,  g_att_hi);  cudaGetSymbolAddress(&al_p,  g_att_lo);

    float* qkv = (float*)qkv_p;
    __nv_bfloat16 *xh = (__nv_bfloat16*)xh_p, *xl = (__nv_bfloat16*)xl_p;
    __nv_bfloat16 *wqh = (__nv_bfloat16*)wqh_p, *wql = (__nv_bfloat16*)wql_p;
    __nv_bfloat16 *woh = (__nv_bfloat16*)woh_p, *wol = (__nv_bfloat16*)wol_p;
    __nv_bfloat16 *ah = (__nv_bfloat16*)ah_p, *al = (__nv_bfloat16*)al_p;

    cudaFuncSetAttribute(gemm_bf16x3, cudaFuncAttributeMaxDynamicSharedMemorySize, GSMEM_SZ);

    // 0) split inputs into bf16 hi/lo
    {
        int n4 = (MTOK * DIM) / 4;
        split_kernel<<<(n4 + 255) / 256, 256>>>(x, xh, xl, n4);
        n4 = (EQKV * DIM) / 4;
        split_kernel<<<(n4 + 255) / 256, 256>>>(w_qkv, wqh, wql, n4);
        n4 = (DIM * DIM) / 4;
        split_kernel<<<(n4 + 255) / 256, 256>>>(w_out, woh, wol, n4);
    }
    // 1) QKV projection: [36864,1024] x [3072,1024]^T
    {
        dim3 grid(EQKV / 128, MTOK / 128);
        gemm_bf16x3<<<grid, 256, GSMEM_SZ>>>(xh, xl, wqh, wql, qkv, nullptr, EQKV, DIM);
    }
    // 2) RoPE + causal attention, writes split bf16 att
    {
        attn_kernel<<<(BB * HWP) * HEADS, 256>>>(qkv, ah, al);
    }
    // 3) Output projection + bias
    {
        dim3 grid(DIM / 128, MTOK / 128);
        gemm_bf16x3<<<grid, 256, GSMEM_SZ>>>(ah, al, woh, wol, out, b_out, DIM, DIM);
    }
}

// round 9
// speedup vs baseline: 2.9458x; 1.0346x over previous
#include <cuda_runtime.h>
#include <cuda_bf16.h>
#include <cstdint>
#include <math.h>

// Problem constants
#define BB    2
#define TT    32
#define HH    18
#define WW    32
#define DIM   1024
#define HEADS 16
#define HD    64
#define HWP   (HH*WW)            // 576
#define MTOK  (BB*TT*HWP)        // 36864 tokens
#define EQKV  (3*HEADS*HD)       // 3072
#define EO    (HEADS*HD)         // 1024

// ---------------- scratch (device globals; no allocation allowed) ----------
__device__ float          g_qkv[(size_t)MTOK * EQKV];
__device__ __nv_bfloat16  g_x_hi[(size_t)MTOK * DIM];
__device__ __nv_bfloat16  g_x_lo[(size_t)MTOK * DIM];
__device__ __nv_bfloat16  g_wqkv_hi[(size_t)EQKV * DIM];
__device__ __nv_bfloat16  g_wqkv_lo[(size_t)EQKV * DIM];
__device__ __nv_bfloat16  g_wout_hi[(size_t)DIM * DIM];
__device__ __nv_bfloat16  g_wout_lo[(size_t)DIM * DIM];
__device__ __nv_bfloat16  g_att_hi[(size_t)MTOK * EO];
__device__ __nv_bfloat16  g_att_lo[(size_t)MTOK * EO];

// ---------------- helpers ---------------------------------------------------
__device__ __forceinline__ uint32_t smem_u32(const void* p) {
    uint32_t a;
    asm("{ .reg .u64 t; cvta.to.shared.u64 t, %1; cvt.u32.u64 %0, t; }" : "=r"(a) : "l"(p));
    return a;
}

// SW64 swizzle: 64-byte rows, 8-row/512B atom (verified helper pattern)
#define SWZ64(off) ((off) ^ (((off) >> 3) & 0x30))

__device__ __forceinline__ void cp16(uint32_t saddr, const void* g) {
    asm volatile("cp.async.cg.shared.global [%0], [%1], 16;" :: "r"(saddr), "l"(g));
}
#define CP_COMMIT() asm volatile("cp.async.commit_group;" ::: "memory")
#define CP_WAIT0()  asm volatile("cp.async.wait_group 0;" ::: "memory")
#define CP_WAIT1()  asm volatile("cp.async.wait_group 1;" ::: "memory")

__device__ __forceinline__ void ldm_x4(uint32_t* r, uint32_t addr) {
    asm volatile("ldmatrix.sync.aligned.m8n8.x4.shared.b16 {%0,%1,%2,%3}, [%4];"
                 : "=r"(r[0]), "=r"(r[1]), "=r"(r[2]), "=r"(r[3]) : "r"(addr));
}

__device__ __forceinline__ void mma16816(float* d, const uint32_t* a, const uint32_t* b) {
    asm volatile("mma.sync.aligned.m16n8k16.row.col.f32.bf16.bf16.f32 "
                 "{%0,%1,%2,%3}, {%4,%5,%6,%7}, {%8,%9}, {%0,%1,%2,%3};"
                 : "+f"(d[0]), "+f"(d[1]), "+f"(d[2]), "+f"(d[3])
                 : "r"(a[0]), "r"(a[1]), "r"(a[2]), "r"(a[3]), "r"(b[0]), "r"(b[1]));
}

// ---------------------------------------------------------------------------
// split: fp32 -> bf16 hi + bf16 lo (residual)
// ---------------------------------------------------------------------------
__global__ void __launch_bounds__(256)
split_kernel(const float* __restrict__ in, __nv_bfloat16* __restrict__ hi,
             __nv_bfloat16* __restrict__ lo, int n4)
{
    int i = blockIdx.x * 256 + threadIdx.x;
    if (i >= n4) return;
    float4 v = ((const float4*)in)[i];
    __nv_bfloat16 h[4], l[4];
    float f[4] = {v.x, v.y, v.z, v.w};
#pragma unroll
    for (int j = 0; j < 4; j++) {
        h[j] = __float2bfloat16(f[j]);
        l[j] = __float2bfloat16(f[j] - __bfloat162float(h[j]));
    }
    ((uint64_t*)hi)[i] = *(const uint64_t*)h;
    ((uint64_t*)lo)[i] = *(const uint64_t*)l;
}

// ---------------------------------------------------------------------------
// FUSED bf16 3-term split GEMM on mma.sync: C[M,N] = A x B^T (+bias)
// CTA tile 128x128, BK=32 (64B rows, SW64 swizzle). Stage = Ahi|Alo|Bhi|Blo
// = 32KB; 3-stage ring = 96KB -> 2 CTAs/SM for bubble overlap.
// 8 warps (2m x 4n), warp tile 64x32. Terms: ah*bh + al*bh + ah*bl.
// ---------------------------------------------------------------------------
#define GBK      32
#define SUB_SZ   8192                  // 128 rows * 64 B
#define SUB_A_LO 8192
#define SUB_B_HI 16384
#define SUB_B_LO 24576
#define STAGE_SZ 32768
#define NSTAGE   3
#define GSMEM_SZ (NSTAGE * STAGE_SZ)   // 98304 per CTA

__device__ __forceinline__ void fill_chunk(
    int cc, uint32_t dst, int tid, int m0, int n0, int K,
    const __nv_bfloat16* __restrict__ Ahi, const __nv_bfloat16* __restrict__ Alo,
    const __nv_bfloat16* __restrict__ Bhi, const __nv_bfloat16* __restrict__ Blo)
{
    const int kk = cc * GBK;
#pragma unroll
    for (int i = 0; i < 2; i++) {
        const int u = tid + i * 256;             // 512 16B-units per sub-tile
        const int row = u >> 2, c16 = u & 3;     // 4 units per 64B row
        const uint32_t so = SWZ64((uint32_t)(row * 64 + c16 * 16));
        const size_t aoff = (size_t)(m0 + row) * K + kk + c16 * 8;
        const size_t boff = (size_t)(n0 + row) * K + kk + c16 * 8;
        cp16(dst + so,            Ahi + aoff);
        cp16(dst + SUB_A_LO + so, Alo + aoff);
        cp16(dst + SUB_B_HI + so, Bhi + boff);
        cp16(dst + SUB_B_LO + so, Blo + boff);
    }
}

__global__ void __launch_bounds__(256, 2)
gemm_bf16x3(const __nv_bfloat16* __restrict__ Ahi, const __nv_bfloat16* __restrict__ Alo,
            const __nv_bfloat16* __restrict__ Bhi, const __nv_bfloat16* __restrict__ Blo,
            float* __restrict__ C, const float* __restrict__ bias, int N, int K)
{
    extern __shared__ char smem[];
    const uint32_t sb = smem_u32(smem);
    const int tid = threadIdx.x;
    const int m0 = blockIdx.y * 128;
    const int n0 = blockIdx.x * 128;
    const int lane = tid & 31;
    const int warp = tid >> 5;
    const int warp_m = warp >> 2;      // 0..1
    const int warp_n = warp & 3;       // 0..3

    float acc[4][4][4];
#pragma unroll
    for (int a = 0; a < 4; a++)
#pragma unroll
        for (int b = 0; b < 4; b++)
#pragma unroll
            for (int c = 0; c < 4; c++) acc[a][b][c] = 0.f;

    const int kchunks = K / GBK;       // 32

    fill_chunk(0, sb, tid, m0, n0, K, Ahi, Alo, Bhi, Blo);
    CP_COMMIT();
    fill_chunk(1, sb + STAGE_SZ, tid, m0, n0, K, Ahi, Alo, Bhi, Blo);
    CP_COMMIT();

    // ldmatrix per-thread address components (pre-swizzle byte offsets, 64B rows)
    const uint32_t a_row_half = (uint32_t)(lane & 15);
    const uint32_t a_koff     = (uint32_t)((lane >> 4) << 4);
    const uint32_t b_row_half = (uint32_t)(((lane >> 4) << 3) + (lane & 7));
    const uint32_t b_koff     = (uint32_t)(((lane >> 3) & 1) << 4);

    for (int cc = 0; cc < kchunks; cc++) {
        if (cc + 1 < kchunks) { CP_WAIT1(); } else { CP_WAIT0(); }
        __syncthreads();
        if (cc + 2 < kchunks) {
            fill_chunk(cc + 2, sb + (uint32_t)((cc + 2) % NSTAGE) * STAGE_SZ,
                       tid, m0, n0, K, Ahi, Alo, Bhi, Blo);
            CP_COMMIT();
        }
        const uint32_t st = sb + (uint32_t)(cc % NSTAGE) * STAGE_SZ;

#pragma unroll
        for (int ks = 0; ks < 2; ks++) {
            uint32_t bh[2][4], bl[2][4];
#pragma unroll
            for (int nt2 = 0; nt2 < 2; nt2++) {
                const uint32_t row = (uint32_t)(warp_n * 32 + nt2 * 16) + b_row_half;
                const uint32_t so = SWZ64(row * 64 + (uint32_t)(ks * 32) + b_koff);
                ldm_x4(bh[nt2], st + SUB_B_HI + so);
                ldm_x4(bl[nt2], st + SUB_B_LO + so);
            }
#pragma unroll
            for (int mt = 0; mt < 4; mt++) {
                uint32_t ah[4], al[4];
                const uint32_t row = (uint32_t)(warp_m * 64 + mt * 16) + a_row_half;
                const uint32_t so = SWZ64(row * 64 + (uint32_t)(ks * 32) + a_koff);
                ldm_x4(ah, st + so);
                ldm_x4(al, st + SUB_A_LO + so);
#pragma unroll
                for (int nt = 0; nt < 4; nt++) {
                    const uint32_t* bph = &bh[nt >> 1][(nt & 1) * 2];
                    const uint32_t* bpl = &bl[nt >> 1][(nt & 1) * 2];
                    mma16816(acc[mt][nt], ah, bph);
                    mma16816(acc[mt][nt], al, bph);
                    mma16816(acc[mt][nt], ah, bpl);
                }
            }
        }
    }

    __syncthreads();

    // epilogue
    const int ln4 = lane >> 2;
    const int lc2 = (lane & 3) * 2;
#pragma unroll
    for (int mt = 0; mt < 4; mt++) {
        const int r0 = m0 + warp_m * 64 + mt * 16 + ln4;
#pragma unroll
        for (int nt = 0; nt < 4; nt++) {
            const int col = n0 + warp_n * 32 + nt * 8 + lc2;
            float bx = 0.f, by = 0.f;
            if (bias) { bx = bias[col]; by = bias[col + 1]; }
            float2 v0 = make_float2(acc[mt][nt][0] + bx, acc[mt][nt][1] + by);
            float2 v1 = make_float2(acc[mt][nt][2] + bx, acc[mt][nt][3] + by);
            *(float2*)(C + (size_t)r0 * N + col)       = v0;
            *(float2*)(C + (size_t)(r0 + 8) * N + col) = v1;
        }
    }
}

// ---------------------------------------------------------------------------
// Attention: one block per (sequence, head). Writes bf16 hi/lo split output.
// ---------------------------------------------------------------------------
__global__ void __launch_bounds__(256)
attn_kernel(const float* __restrict__ qkv,
            __nv_bfloat16* __restrict__ att_hi, __nv_bfloat16* __restrict__ att_lo)
{
    const int blk  = blockIdx.x;
    const int head = blk & 15;
    const int n    = blk >> 4;
    const int b    = n / HWP;
    const int hw   = n - b * HWP;
    const size_t base_tok = (size_t)b * (TT * HWP) + hw;

    __shared__ float Qs[32][65];
    __shared__ float Ks[32][65];
    __shared__ float Vs[32][64];
    __shared__ float Ss[32][33];

    const int tid = threadIdx.x;

    for (int i = tid; i < 32 * 64; i += 256) {
        const int t = i >> 6, d = i & 63;
        const size_t tok = base_tok + (size_t)t * HWP;
        const float* p = qkv + tok * EQKV + head * HD + d;
        Qs[t][d] = p[0];
        Ks[t][d] = p[1024];
        Vs[t][d] = p[2048];
    }
    __syncthreads();

    for (int i = tid; i < 2 * 32 * 16; i += 256) {
        const int mat = i >> 9;
        const int rem = i & 511;
        const int t = rem >> 4, j = rem & 15;
        const float freq = powf(10000.0f, -(float)j / 16.0f);
        const float ang = (float)t * freq;
        const float c = cosf(ang), s = sinf(ang);
        float (*P)[65] = mat ? Ks : Qs;
        const float x0 = P[t][2 * j];
        const float x1 = P[t][2 * j + 1];
        P[t][2 * j]     = x0 * c - x1 * s;
        P[t][2 * j + 1] = x1 * c + x0 * s;
    }
    __syncthreads();

    const int r = tid >> 4, c = tid & 15;
    {
        float s00 = 0.f, s01 = 0.f, s10 = 0.f, s11 = 0.f;
#pragma unroll 16
        for (int d = 0; d < 64; d++) {
            const float q0 = Qs[2 * r][d],     q1 = Qs[2 * r + 1][d];
            const float k0 = Ks[2 * c][d],     k1 = Ks[2 * c + 1][d];
            s00 += q0 * k0; s01 += q0 * k1;
            s10 += q1 * k0; s11 += q1 * k1;
        }
        Ss[2 * r][2 * c]         = s00;
        Ss[2 * r][2 * c + 1]     = s01;
        Ss[2 * r + 1][2 * c]     = s10;
        Ss[2 * r + 1][2 * c + 1] = s11;
    }
    __syncthreads();

    const int warp = tid >> 5, lane = tid & 31;
    const float scale = 0.125f;
#pragma unroll
    for (int qi = 0; qi < 4; qi++) {
        const int q = warp * 4 + qi;
        float s = (lane <= q) ? Ss[q][lane] * scale : -INFINITY;
        float m = s;
#pragma unroll
        for (int o = 16; o > 0; o >>= 1)
            m = fmaxf(m, __shfl_xor_sync(0xffffffffu, m, o));
        const float e = expf(s - m);
        float sum = e;
#pragma unroll
        for (int o = 16; o > 0; o >>= 1)
            sum += __shfl_xor_sync(0xffffffffu, sum, o);
        Ss[q][lane] = e / sum;
    }
    __syncthreads();

    float o0[4] = {0.f, 0.f, 0.f, 0.f};
    float o1[4] = {0.f, 0.f, 0.f, 0.f};
#pragma unroll 8
    for (int k = 0; k < 32; k++) {
        const float p0 = Ss[2 * r][k];
        const float p1 = Ss[2 * r + 1][k];
#pragma unroll
        for (int j = 0; j < 4; j++) {
            const float v = Vs[k][4 * c + j];
            o0[j] += p0 * v;
            o1[j] += p1 * v;
        }
    }
#pragma unroll
    for (int i = 0; i < 2; i++) {
        const int t = 2 * r + i;
        const size_t tok = base_tok + (size_t)t * HWP;
        const size_t base = tok * EO + head * HD + 4 * c;
        const float* src = i ? o1 : o0;
        __nv_bfloat16 h[4], l[4];
#pragma unroll
        for (int j = 0; j < 4; j++) {
            h[j] = __float2bfloat16(src[j]);
            l[j] = __float2bfloat16(src[j] - __bfloat162float(h[j]));
        }
        *(uint64_t*)(att_hi + base) = *(const uint64_t*)h;
        *(uint64_t*)(att_lo + base) = *(const uint64_t*)l;
    }
}

// ---------------------------------------------------------------------------
extern "C" void kernel_launch(void* const* d_in, const int* in_sizes, int n_in,
                              void* d_out, int out_size)
{
    const float* x     = (const float*)d_in[0];
    const float* w_qkv = (const float*)d_in[1];
    const float* w_out = (const float*)d_in[2];
    const float* b_out = (const float*)d_in[3];
    float* out = (float*)d_out;

    void *qkv_p, *xh_p, *xl_p, *wqh_p, *wql_p, *woh_p, *wol_p, *ah_p, *al_p;
    cudaGetSymbolAddress(&qkv_p, g_qkv);
    cudaGetSymbolAddress(&xh_p,  g_x_hi);    cudaGetSymbolAddress(&xl_p,  g_x_lo);
    cudaGetSymbolAddress(&wqh_p, g_wqkv_hi); cudaGetSymbolAddress(&wql_p, g_wqkv_lo);
    cudaGetSymbolAddress(&woh_p, g_wout_hi); cudaGetSymbolAddress(&wol_p, g_wout_lo);
    cudaGetSymbolAddress(&ah_p,  g_att_hi);  cudaGetSymbolAddress(&al_p,  g_att_lo);

    float* qkv = (float*)qkv_p;
    __nv_bfloat16 *xh = (__nv_bfloat16*)xh_p, *xl = (__nv_bfloat16*)xl_p;
    __nv_bfloat16 *wqh = (__nv_bfloat16*)wqh_p, *wql = (__nv_bfloat16*)wql_p;
    __nv_bfloat16 *woh = (__nv_bfloat16*)woh_p, *wol = (__nv_bfloat16*)wol_p;
    __nv_bfloat16 *ah = (__nv_bfloat16*)ah_p, *al = (__nv_bfloat16*)al_p;

    cudaFuncSetAttribute(gemm_bf16x3, cudaFuncAttributeMaxDynamicSharedMemorySize, GSMEM_SZ);

    // 0) split inputs into bf16 hi/lo
    {
        int n4 = (MTOK * DIM) / 4;
        split_kernel<<<(n4 + 255) / 256, 256>>>(x, xh, xl, n4);
        n4 = (EQKV * DIM) / 4;
        split_kernel<<<(n4 + 255) / 256, 256>>>(w_qkv, wqh, wql, n4);
        n4 = (DIM * DIM) / 4;
        split_kernel<<<(n4 + 255) / 256, 256>>>(w_out, woh, wol, n4);
    }
    // 1) QKV projection: [36864,1024] x [3072,1024]^T
    {
        dim3 grid(EQKV / 128, MTOK / 128);
        gemm_bf16x3<<<grid, 256, GSMEM_SZ>>>(xh, xl, wqh, wql, qkv, nullptr, EQKV, DIM);
    }
    // 2) RoPE + causal attention, writes split bf16 att
    {
        attn_kernel<<<(BB * HWP) * HEADS, 256>>>(qkv, ah, al);
    }
    // 3) Output projection + bias
    {
        dim3 grid(DIM / 128, MTOK / 128);
        gemm_bf16x3<<<grid, 256, GSMEM_SZ>>>(ah, al, woh, wol, out, b_out, DIM, DIM);
    }
}